// round 7
// baseline (speedup 1.0000x reference)
#include <cuda_runtime.h>
#include <stdint.h>

// Problem constants (fixed shapes from reference): x = (32, 3, 512, 512) f32.
// 96 images, 8x8 tile grid, tiles of 64x64 (area 4096), 256 bins, clip=32.
#define N_IMG      96
#define IMG_H      512
#define IMG_W      512
#define IMG_PIX    (IMG_H * IMG_W)          // 262144
#define GRID_G     8
#define TILE_H     64
#define TILE_W     64
#define NBINS      256
#define CLIP_V     32
#define N_TILES    (N_IMG * GRID_G * GRID_G) // 6144

// Scratch: quantized u8 image + per-tile LUTs (u8). __device__ globals (no alloc).
__device__ uint8_t g_img[(size_t)N_IMG * IMG_PIX];        // 24 MiB
__device__ uint8_t g_lut[(size_t)N_TILES * NBINS];        // 1.5 MiB

// ---------------------------------------------------------------------------
// Kernel 1: per-tile histogram -> clip -> redistribute -> cdf -> LUT,
// quantizing the f32 image into u8 scratch on the way through.
// One block (256 threads) per tile.
// Histogram layout s_hist[bin*32 + lane]: atomic bank == lane -> ZERO bank
// conflicts and ZERO same-address collisions within a warp, by construction.
// Init/merge walk [tid*32 + (tid+j)&31] -> also conflict-free.
// ---------------------------------------------------------------------------
__global__ void __launch_bounds__(256)
clahe_hist_lut_kernel(const float* __restrict__ x)
{
    const int tid     = threadIdx.x;        // 0..255, also "my bin"
    const int tile_id = blockIdx.x;         // 0..6143
    const int bc      = tile_id >> 6;       // image index
    const int t       = tile_id & 63;
    const int gy      = t >> 3;
    const int gx      = t & 7;
    const int lane    = tid & 31, wid = tid >> 5;

    __shared__ int s_hist[NBINS * 32];      // 32 KB, [bin][lane]
    __shared__ int s_excess;
    __shared__ int s_warp[8];

    // conflict-free zero-init: thread tid owns row tid, rotated column order
    {
        int* row = s_hist + tid * 32;
        #pragma unroll
        for (int j = 0; j < 32; j++) row[(tid + j) & 31] = 0;
    }
    if (tid == 0) s_excess = 0;
    __syncthreads();

    const float* img  = x + (size_t)bc * IMG_PIX;
    uint8_t*     dimg = g_img + (size_t)bc * IMG_PIX;

    const int row0 = gy * TILE_H;
    const int col0 = gx * TILE_W;

    // Batch all 16 pixel loads first (MLP = 4 x float4)
    float4 v[4];
    size_t offs[4];
    #pragma unroll
    for (int i = 0; i < 4; i++) {
        int q  = tid + i * 256;             // float4 index within tile: 0..1023
        int r  = q >> 4;                    // tile row (16 float4 per 64-px row)
        int c4 = q & 15;
        offs[i] = (size_t)(row0 + r) * IMG_W + col0 + c4 * 4;
        v[i]    = *(const float4*)(img + offs[i]);
    }
    #pragma unroll
    for (int i = 0; i < 4; i++) {
        // match jnp.round (round-half-even) of clip(x,0,1)*255
        unsigned p0 = (unsigned)rintf(__saturatef(v[i].x) * 255.0f);
        unsigned p1 = (unsigned)rintf(__saturatef(v[i].y) * 255.0f);
        unsigned p2 = (unsigned)rintf(__saturatef(v[i].z) * 255.0f);
        unsigned p3 = (unsigned)rintf(__saturatef(v[i].w) * 255.0f);
        atomicAdd(&s_hist[p0 * 32 + lane], 1);   // bank == lane: conflict-free
        atomicAdd(&s_hist[p1 * 32 + lane], 1);
        atomicAdd(&s_hist[p2 * 32 + lane], 1);
        atomicAdd(&s_hist[p3 * 32 + lane], 1);
        unsigned packed = p0 | (p1 << 8) | (p2 << 16) | (p3 << 24);
        *(unsigned*)(dimg + offs[i]) = packed;
    }
    __syncthreads();

    // conflict-free merge: thread tid sums its bin's 32 lane-columns, rotated
    int h = 0;
    {
        const int* row = s_hist + tid * 32;
        #pragma unroll
        for (int j = 0; j < 32; j++) h += row[(tid + j) & 31];
    }

    // clip + excess reduction
    int clipped = min(h, CLIP_V);
    int over    = h - clipped;
    #pragma unroll
    for (int o = 16; o > 0; o >>= 1)
        over += __shfl_down_sync(0xffffffffu, over, o);
    if (lane == 0) atomicAdd(&s_excess, over);
    __syncthreads();

    const int excess    = s_excess;
    const int batch_add = excess >> 8;           // excess / 256
    const int residual  = excess & 255;          // excess % 256
    const int step      = max(256 / max(residual, 1), 1);
    const int extra     = ((tid % step) == 0 && (tid / step) < residual) ? 1 : 0;
    int vv = clipped + batch_add + extra;

    // inclusive scan over 256 bins (warp scan + warp-sum scan)
    int sv = vv;
    #pragma unroll
    for (int o = 1; o < 32; o <<= 1) {
        int n = __shfl_up_sync(0xffffffffu, sv, o);
        if (lane >= o) sv += n;
    }
    if (lane == 31) s_warp[wid] = sv;
    __syncthreads();
    if (wid == 0 && lane < 8) {
        int w = s_warp[lane];
        #pragma unroll
        for (int o = 1; o < 8; o <<= 1) {
            int n = __shfl_up_sync(0x000000ffu, w, o);
            if (lane >= o) w += n;
        }
        s_warp[lane] = w;
    }
    __syncthreads();
    int cdf = sv + (wid ? s_warp[wid - 1] : 0);   // 1..4096

    // lut = clip(round(cdf * 255/4096), 0, 255); exact in f32, rintf = half-even
    float lf = rintf((float)cdf * (255.0f / 4096.0f));
    int   li = min(max((int)lf, 0), 255);
    g_lut[(size_t)tile_id * NBINS + tid] = (uint8_t)li;
}

// ---------------------------------------------------------------------------
// Kernel 2: apply LUTs with bilinear tile interpolation.
// One block (256 threads) per 16-row half-band (3072 blocks).
// Fused 4-way LUT: s_comb[pair][v] = l11 | l12<<8 | l21<<16 | l22<<24 ->
// ONE u32 LDS gather per pixel + exact integer DP4A bilinear.
// ---------------------------------------------------------------------------
__global__ void __launch_bounds__(256)
clahe_apply_kernel(float* __restrict__ out)
{
    const int tid  = threadIdx.x;
    const int blk  = blockIdx.x;        // 0 .. 96*32-1
    const int bc   = blk >> 5;
    const int hb   = blk & 31;          // half-band index (16 rows each)
    const int y0   = hb * 16;

    // tile-row pair for this half-band (constant within the band)
    const int i1u = (hb - 2) >> 2;
    const int ty1 = max(i1u, 0);
    const int ty2 = min(i1u + 1, GRID_G - 1);

    __shared__ uint8_t  s_lut[2][GRID_G * NBINS];   // 2 x 2048 B staging
    __shared__ unsigned s_comb[9 * NBINS];          // fused 4-LUT, 9 col-pairs

    // stage the two LUT rows (2048 B each)
    {
        const uint4* lutA = (const uint4*)(g_lut + ((size_t)(bc * GRID_G + ty1) * GRID_G) * NBINS);
        const uint4* lutB = (const uint4*)(g_lut + ((size_t)(bc * GRID_G + ty2) * GRID_G) * NBINS);
        if (tid < 128) ((uint4*)s_lut[0])[tid]       = __ldcg(&lutA[tid]);
        else           ((uint4*)s_lut[1])[tid - 128] = __ldcg(&lutB[tid - 128]);
    }
    __syncthreads();

    // build fused table: 9 column pairs, thread tid handles bin v = tid
    #pragma unroll
    for (int p = 0; p < 9; p++) {
        int tx1 = max(p - 1, 0);
        int tx2 = min(p, GRID_G - 1);
        unsigned l11 = s_lut[0][tx1 * NBINS + tid];
        unsigned l12 = s_lut[0][tx2 * NBINS + tid];
        unsigned l21 = s_lut[1][tx1 * NBINS + tid];
        unsigned l22 = s_lut[1][tx2 * NBINS + tid];
        s_comb[p * NBINS + tid] = l11 | (l12 << 8) | (l21 << 16) | (l22 << 24);
    }
    __syncthreads();

    const uint8_t* dimg = g_img + (size_t)bc * IMG_PIX + (size_t)y0 * IMG_W;
    float*         o    = out   + (size_t)bc * IMG_PIX + (size_t)y0 * IMG_W;

    // per-thread x-position is loop-invariant (c4 = tid & 127)
    const int c4   = tid & 127;
    const int r0   = tid >> 7;
    const int x0   = c4 * 4;
    const int pair = (x0 + 32) >> 6;              // groups never straddle pairs
    const int iax0 = (x0 + 32) & 63;
    const unsigned* comb = &s_comb[pair * NBINS];

    unsigned wAv[4];
    #pragma unroll
    for (int j = 0; j < 4; j++) {
        int iax = iax0 + j;
        wAv[j] = (unsigned)(64 - iax) | ((unsigned)iax << 8);
    }

    #pragma unroll
    for (int it = 0; it < 8; it++) {
        int r    = r0 + it * 2;
        int iay  = (y0 + r + 32) & 63;
        int wy1i = 64 - iay;

        unsigned p = *(const unsigned*)(dimg + (size_t)r * IMG_W + x0);

        float4 res;
        float* rp = (float*)&res;
        #pragma unroll
        for (int j = 0; j < 4; j++) {
            unsigned L = comb[(p >> (8 * j)) & 255];
            int A = __dp4a(L, wAv[j], 0u);        // top-row horiz interp
            int B = __dp4a(L, wAv[j] << 16, 0u);  // bottom-row horiz interp
            int N = A * wy1i + B * iay;           // res * 4096, exact

            // round-half-even(N/4096): N < 2^20 so i2f and *2^-12 are exact
            float kf = rintf((float)N * 0x1p-12f);
            rp[j] = kf * (1.0f / 255.0f);         // <= 1 ulp vs exact div
        }
        *(float4*)(o + (size_t)r * IMG_W + x0) = res;
    }
}

// ---------------------------------------------------------------------------
extern "C" void kernel_launch(void* const* d_in, const int* in_sizes, int n_in,
                              void* d_out, int out_size)
{
    const float* x   = (const float*)d_in[0];
    float*       out = (float*)d_out;
    (void)in_sizes; (void)n_in; (void)out_size;

    clahe_hist_lut_kernel<<<N_TILES, 256>>>(x);
    clahe_apply_kernel<<<N_IMG * 32, 256>>>(out);
}